// round 4
// baseline (speedup 1.0000x reference)
#include <cuda_runtime.h>
#include <cuda_bf16.h>
#include <cstdint>

// MaxUnpooling2D scatter-add, per-batch L2-resident (zero b, then scatter b),
// with 128-bit one-hot vector reductions (red.global.add.v4.f32) so the LTS
// atomic ALU — the measured bottleneck at 1 op/2cyc/partition — handles 4
// floats per op instead of 1.
//
// inputs:  d_in[0] float32, (8, 128, 128, 256)
// indices: d_in[1] int32, same shape, values in [0, 2^24)
// output:  float32, (8, 256, 256, 256), zero-init, duplicate-summing scatter.

static constexpr int B         = 8;
static constexpr int IN_PER_B  = 1 << 22;   // 16 MB f32 per batch
static constexpr int OUT_PER_B = 1 << 24;   // 64 MB f32 per batch

__global__ void __launch_bounds__(256)
zero_batch_kernel(float4* __restrict__ out4)
{
    int i = blockIdx.x * blockDim.x + threadIdx.x;
    out4[i] = make_float4(0.f, 0.f, 0.f, 0.f);
}

__device__ __forceinline__ void red_v4_onehot(float* __restrict__ out, int x, float v)
{
    // 16B-aligned base slot; one-hot lane = x & 3. Adding +0.0f to the other
    // three lanes is value-preserving (only -0.0 -> +0.0, which is exact 0 diff).
    float* p = out + (x & ~3);
    int lane = x & 3;
    float a = (lane == 0) ? v : 0.f;
    float b = (lane == 1) ? v : 0.f;
    float c = (lane == 2) ? v : 0.f;
    float d = (lane == 3) ? v : 0.f;
    asm volatile("red.global.add.v4.f32 [%0], {%1, %2, %3, %4};"
                 :: "l"(p), "f"(a), "f"(b), "f"(c), "f"(d) : "memory");
}

__global__ void __launch_bounds__(256)
scatter_batch_kernel(const float4* __restrict__ vals4,
                     const int4*  __restrict__ idx4,
                     float* __restrict__ out)
{
    int i = blockIdx.x * blockDim.x + threadIdx.x;
    float4 v = __ldcs(vals4 + i);
    int4   x = __ldcs(idx4 + i);
    red_v4_onehot(out, x.x, v.x);
    red_v4_onehot(out, x.y, v.y);
    red_v4_onehot(out, x.z, v.z);
    red_v4_onehot(out, x.w, v.w);
}

extern "C" void kernel_launch(void* const* d_in, const int* in_sizes, int n_in,
                              void* d_out, int out_size)
{
    const float* vals = (const float*)d_in[0];
    const int*   idx  = (const int*)d_in[1];
    float* out = (float*)d_out;

    const int zero_blocks    = (OUT_PER_B / 4) / 256;  // 16384
    const int scatter_blocks = (IN_PER_B  / 4) / 256;  // 4096

    for (int b = 0; b < B; b++) {
        zero_batch_kernel<<<zero_blocks, 256>>>(
            (float4*)(out + (size_t)b * OUT_PER_B));
        scatter_batch_kernel<<<scatter_blocks, 256>>>(
            (const float4*)(vals + (size_t)b * IN_PER_B),
            (const int4*)(idx + (size_t)b * IN_PER_B),
            out + (size_t)b * OUT_PER_B);
    }
}

// round 5
// speedup vs baseline: 1.3072x; 1.3072x over previous
#include <cuda_runtime.h>
#include <cuda_bf16.h>
#include <cstdint>

// MaxUnpooling2D scatter-add, pipelined at half-batch (32MB) granularity so the
// zero fill of the NEXT half region overlaps the atomic scatter of the CURRENT
// half while the combined L2 working set (32+32MB) stays resident.
//
//   zero(b0.h0)
//   [scatter(b0,h0) || zero(b0.h1)] [scatter(b0,h1) || zero(b1.h0)] ...
//   ... [scatter(b7,h1)]
//
// Scatter is LTS atomic-message-rate bound (~150G msg/s measured); zeroing is
// LTS write-path bound -> they overlap. Each scatter pass re-reads the batch's
// idx/val stream (2nd pass hits L2) and predicates REDs on (idx>>23)==phase.

static constexpr int B         = 8;
static constexpr int IN_PER_B  = 1 << 22;   // elems per batch input (16 MB f32)
static constexpr int OUT_PER_B = 1 << 24;   // elems per batch output (64 MB f32)
static constexpr int HALF_OUT  = OUT_PER_B / 2;            // 2^23 elems, 32 MB

static constexpr int SCATTER_BLOCKS   = (IN_PER_B / 4) / 256;   // 4096
static constexpr int ZERO_HALF_BLOCKS = (HALF_OUT / 4) / 256;   // 8192

__global__ void __launch_bounds__(256)
zero_half_kernel(float4* __restrict__ out4)
{
    int i = blockIdx.x * blockDim.x + threadIdx.x;
    out4[i] = make_float4(0.f, 0.f, 0.f, 0.f);
}

// Blocks [0, SCATTER_BLOCKS): scatter elements of `phase` half of batch region.
// Blocks [SCATTER_BLOCKS, +ZERO_HALF_BLOCKS): zero the next 32MB half region.
__global__ void __launch_bounds__(256)
pipe_half_kernel(const float4* __restrict__ vals4,
                 const int4*  __restrict__ idx4,
                 float* __restrict__ out_scatter,   // batch base
                 int phase,                          // 0: idx<2^23, 1: idx>=2^23
                 float4* __restrict__ out_zero)      // 32MB region or nullptr
{
    int bid = blockIdx.x;
    if (bid < SCATTER_BLOCKS) {
        int i = bid * 256 + threadIdx.x;
        float4 v = __ldcs(vals4 + i);
        int4   x = __ldcs(idx4 + i);
        if ((x.x >> 23) == phase) atomicAdd(out_scatter + x.x, v.x);
        if ((x.y >> 23) == phase) atomicAdd(out_scatter + x.y, v.y);
        if ((x.z >> 23) == phase) atomicAdd(out_scatter + x.z, v.z);
        if ((x.w >> 23) == phase) atomicAdd(out_scatter + x.w, v.w);
    } else {
        int i = (bid - SCATTER_BLOCKS) * 256 + threadIdx.x;
        out_zero[i] = make_float4(0.f, 0.f, 0.f, 0.f);
    }
}

extern "C" void kernel_launch(void* const* d_in, const int* in_sizes, int n_in,
                              void* d_out, int out_size)
{
    const float* vals = (const float*)d_in[0];
    const int*   idx  = (const int*)d_in[1];
    float* out = (float*)d_out;

    // Prologue: zero batch 0, half 0.
    zero_half_kernel<<<ZERO_HALF_BLOCKS, 256>>>((float4*)out);

    // 16 half-steps: step s scatters (b = s/2, h = s&1) and zeroes half s+1.
    for (int s = 0; s < 2 * B; s++) {
        int b = s >> 1;
        int h = s & 1;
        const float4* v4 = (const float4*)(vals + (size_t)b * IN_PER_B);
        const int4*   x4 = (const int4*)(idx + (size_t)b * IN_PER_B);
        float* out_b = out + (size_t)b * OUT_PER_B;

        if (s + 1 < 2 * B) {
            float4* zdst = (float4*)(out + (size_t)(s + 1) * HALF_OUT);
            pipe_half_kernel<<<SCATTER_BLOCKS + ZERO_HALF_BLOCKS, 256>>>(
                v4, x4, out_b, h, zdst);
        } else {
            pipe_half_kernel<<<SCATTER_BLOCKS, 256>>>(
                v4, x4, out_b, h, nullptr);
        }
    }
}